// round 15
// baseline (speedup 1.0000x reference)
#include <cuda_runtime.h>
#include <cuda_fp16.h>
#include <math.h>
#include <stdint.h>

#define S_   1024
#define HD_  2048
#define L_   2
#define G_   4
#define D_   64
#define GS_  8
#define GD_  256
#define QKV_ 768
#define FF_  8192
#define V_   38400

// ---------------- scratch ----------------
__device__ float g_Wqkv[L_ * HD_ * QKV_];
__device__ float g_bqkv[L_ * QKV_];
__device__ float g_Wo_r[L_ * GD_ * HD_];
__device__ float g_h  [S_ * HD_];
__device__ float g_t2 [S_ * HD_];
__device__ float g_sc [G_ * S_ * S_];
__device__ __half g_hh  [S_ * HD_];
__device__ __half g_qkvh[S_ * QKV_];
__device__ __half g_vth [GD_ * S_];
__device__ __half g_sch [G_ * S_ * S_];
__device__ __half g_ctxh[S_ * GD_];
__device__ __half g_a1h [S_ * FF_];
__device__ __half g_WqkvTh[L_ * QKV_ * HD_];
__device__ __half g_WoTh  [L_ * HD_ * GD_];
__device__ __half g_W1Th  [L_ * FF_ * HD_];
__device__ __half g_W2Th  [L_ * HD_ * FF_];
__device__ __half g_WheadTh[(long long)V_ * HD_];

// ---------------- helpers ----------------
__device__ __forceinline__ void cp16(uint32_t d, const void* g) {
    asm volatile("cp.async.cg.shared.global [%0], [%1], 16;\n" :: "r"(d), "l"(g));
}
__device__ __forceinline__ void ldx4(uint32_t* r, uint32_t addr) {
    asm volatile("ldmatrix.sync.aligned.m8n8.x4.shared.b16 {%0,%1,%2,%3}, [%4];"
                 : "=r"(r[0]), "=r"(r[1]), "=r"(r[2]), "=r"(r[3]) : "r"(addr));
}
__device__ __forceinline__ void mma_f16(float c[4], const uint32_t a[4], const uint32_t b[2]) {
    asm volatile(
        "mma.sync.aligned.m16n8k16.row.col.f32.f16.f16.f32 "
        "{%0,%1,%2,%3}, {%4,%5,%6,%7}, {%8,%9}, {%0,%1,%2,%3};"
        : "+f"(c[0]), "+f"(c[1]), "+f"(c[2]), "+f"(c[3])
        : "r"(a[0]), "r"(a[1]), "r"(a[2]), "r"(a[3]), "r"(b[0]), "r"(b[1]));
}

// ---------------------------------------------------------------------------
// fp16 GEMM via ldmatrix-fed mma.sync m16n8k16, fp32 accumulate.
//   C[M,N] = alpha * A[M,K] @ Bt[N,K]^T (+bias)
// A,Bt half, k-contiguous rows. K mult of 64, M mult of 128, N mult of BN_.
// Block 128 x BN_ x 64, 128 threads (2x2 warps, warp tile 64 x BN_/2).
// 3-stage cp.async pipeline, ONE __syncthreads per 64-K chunk:
//   iter i: wait(chunk i) -> sync -> issue load(i+2) into buffer freed by
//   compute(i-1) -> compute(i).  Two compute phases of load cover.
// smem rows = 64 halves (128B), 16B chunks XOR-swizzled (ch ^= row&7).
// grid: x = M-tile, y = N-tile, z = batch/ksplit.
// flags: 1=relu, 4=atomicAdd(fp32 C), 8=C is __half
// ---------------------------------------------------------------------------
template<int BN_>
__global__ __launch_bounds__(128, 2) void gemm_h(
    const __half* __restrict__ A, long long lda, long long sA,
    const __half* __restrict__ Bt, long long ldb, long long sB,
    const float* __restrict__ bias,
    void* __restrict__ Cv, long long ldc, long long sC,
    int kchunks, long long kbz, float alpha, int flags)
{
    constexpr int NI = BN_ / 16;
    constexpr int ABYTES = 128 * 128;
    constexpr int STAGE  = ABYTES + BN_ * 128;
    extern __shared__ char dsm[];
    const uint32_t base = (uint32_t)__cvta_generic_to_shared(dsm);

    const long long bz = blockIdx.z;
    A  += bz * sA;
    Bt += bz * sB;
    const long long kb = bz * kbz;

    const int tid  = threadIdx.x;
    const int lane = tid & 31;
    const int warp = tid >> 5;
    const int wm   = (warp & 1) * 64;
    const int wn   = (warp >> 1) * (BN_ / 2);
    const int gid  = lane >> 2;
    const int tg   = lane & 3;
    const int row0 = blockIdx.x * 128;
    const int col0 = blockIdx.y * BN_;

    const int rowA = lane & 15;
    const int acb  = (lane >> 4) & 1;
    const int rowB = (lane & 7) + ((lane >> 4) << 3);
    const int bcb  = (lane >> 3) & 1;
    const uint32_t amask = (uint32_t)(rowA & 7);
    const uint32_t bmask = (uint32_t)(rowB & 7);

    const int T = kchunks;

    auto load_chunk = [&](int i, int buf) {
        const long long k0 = kb + (long long)i * 64;
        const uint32_t sb = base + buf * STAGE;
#pragma unroll
        for (int p = 0; p < 8; p++) {                       // A: 128 rows x 8 chunks
            int v = p * 128 + tid;
            int row = v >> 3, ch = v & 7;
            cp16(sb + (uint32_t)(row * 128 + ((ch ^ (row & 7)) << 4)),
                 A + (long long)(row0 + row) * lda + k0 + ch * 8);
        }
#pragma unroll
        for (int p = 0; p < BN_ / 16; p++) {                // B: BN rows x 8 chunks
            int v = p * 128 + tid;
            int row = v >> 3, ch = v & 7;
            cp16(sb + (uint32_t)(ABYTES + row * 128 + ((ch ^ (row & 7)) << 4)),
                 Bt + (long long)(col0 + row) * ldb + k0 + ch * 8);
        }
        asm volatile("cp.async.commit_group;\n" ::);
    };

    float acc[4][NI][4];
#pragma unroll
    for (int mi = 0; mi < 4; mi++)
#pragma unroll
        for (int ni = 0; ni < NI; ni++)
#pragma unroll
            for (int c = 0; c < 4; c++) acc[mi][ni][c] = 0.f;

    // prologue: 2 chunks in flight
    load_chunk(0, 0);
    if (T > 1) load_chunk(1, 1);

    for (int i = 0; i < T; i++) {
        // ensure chunk i landed (at most one newer group may stay pending)
        if (i + 1 < T) asm volatile("cp.async.wait_group 1;\n" ::);
        else           asm volatile("cp.async.wait_group 0;\n" ::);
        __syncthreads();   // chunk i visible to all; compute(i-1) done by all
        if (i + 2 < T) load_chunk(i + 2, (i + 2) % 3);   // reuse buffer of i-1

        const int buf = i % 3;
        const uint32_t Ab = base + buf * STAGE;
        const uint32_t Bb = Ab + ABYTES;

#pragma unroll
        for (int ks = 0; ks < 4; ks++) {        // 4 k16 slices per 64-k chunk
            const uint32_t ca = (uint32_t)(ks * 2 + acb);
            const uint32_t cb = (uint32_t)(ks * 2 + bcb);
            uint32_t afr[4][4];
#pragma unroll
            for (int mi = 0; mi < 4; mi++) {
                uint32_t r = (uint32_t)(wm + mi * 16 + rowA);
                ldx4(afr[mi], Ab + r * 128 + ((ca ^ amask) << 4));
            }
            uint32_t bfr[NI][2];
#pragma unroll
            for (int p = 0; p < NI / 2; p++) {
                uint32_t r = (uint32_t)(wn + p * 16 + rowB);
                uint32_t q[4];
                ldx4(q, Bb + r * 128 + ((cb ^ bmask) << 4));
                bfr[2 * p][0] = q[0]; bfr[2 * p][1] = q[1];
                bfr[2 * p + 1][0] = q[2]; bfr[2 * p + 1][1] = q[3];
            }
#pragma unroll
            for (int mi = 0; mi < 4; mi++)
#pragma unroll
                for (int ni = 0; ni < NI; ni++)
                    mma_f16(acc[mi][ni], afr[mi], bfr[ni]);
        }
    }

    float*  Cf = (float*)Cv + bz * sC;
    __half* Ch = (__half*)Cv + bz * sC;
#pragma unroll
    for (int mi = 0; mi < 4; mi++) {
        int m0 = row0 + wm + mi * 16 + gid;
#pragma unroll
        for (int ni = 0; ni < NI; ni++) {
            int n = col0 + wn + ni * 8 + tg * 2;
            float v0 = alpha * acc[mi][ni][0];
            float v1 = alpha * acc[mi][ni][1];
            float v2 = alpha * acc[mi][ni][2];
            float v3 = alpha * acc[mi][ni][3];
            if (flags & 4) {
                atomicAdd(Cf + (long long)m0 * ldc + n, v0);
                atomicAdd(Cf + (long long)m0 * ldc + n + 1, v1);
                atomicAdd(Cf + (long long)(m0 + 8) * ldc + n, v2);
                atomicAdd(Cf + (long long)(m0 + 8) * ldc + n + 1, v3);
            } else {
                if (bias) {
                    float b0 = bias[n], b1 = bias[n + 1];
                    v0 += b0; v1 += b1; v2 += b0; v3 += b1;
                }
                if (flags & 1) {
                    v0 = fmaxf(v0, 0.f); v1 = fmaxf(v1, 0.f);
                    v2 = fmaxf(v2, 0.f); v3 = fmaxf(v3, 0.f);
                }
                if (flags & 8) {
                    *(__half2*)(Ch + (long long)m0 * ldc + n)       = __floats2half2_rn(v0, v1);
                    *(__half2*)(Ch + (long long)(m0 + 8) * ldc + n) = __floats2half2_rn(v2, v3);
                } else {
                    *(float2*)(Cf + (long long)m0 * ldc + n)       = make_float2(v0, v1);
                    *(float2*)(Cf + (long long)(m0 + 8) * ldc + n) = make_float2(v2, v3);
                }
            }
        }
    }
}

// ---------------- elementwise kernels ----------------
__global__ __launch_bounds__(256) void softmax_kernel(
    const float* __restrict__ Srows, __half* __restrict__ Orows, int T)
{
    const float* row = Srows + (long long)blockIdx.x * T;
    __half* orow = Orows + (long long)blockIdx.x * T;
    __shared__ float red[256];
    int tid = threadIdx.x;
    float m = -INFINITY;
    for (int i = tid; i < T; i += 256) m = fmaxf(m, row[i]);
    red[tid] = m; __syncthreads();
    for (int s = 128; s > 0; s >>= 1) { if (tid < s) red[tid] = fmaxf(red[tid], red[tid + s]); __syncthreads(); }
    m = red[0]; __syncthreads();
    float sum = 0.f;
    float ev[4];
#pragma unroll
    for (int j = 0; j < 4; j++) {
        ev[j] = expf(row[tid + j * 256] - m);
        sum += ev[j];
    }
    red[tid] = sum; __syncthreads();
    for (int s = 128; s > 0; s >>= 1) { if (tid < s) red[tid] += red[tid + s]; __syncthreads(); }
    float inv = 1.f / red[0];
#pragma unroll
    for (int j = 0; j < 4; j++)
        orow[tid + j * 256] = __float2half(ev[j] * inv);
}

__global__ __launch_bounds__(256) void ln_kernel(
    const float* __restrict__ X, const float* __restrict__ R,
    const float* __restrict__ g, const float* __restrict__ b,
    float* __restrict__ O, __half* __restrict__ O2)
{
    long long off = (long long)blockIdx.x * HD_;
    __shared__ float red[256];
    int tid = threadIdx.x;
    float xv[8];
    float lsum = 0.f;
#pragma unroll
    for (int i = 0; i < 8; i++) {
        int c = tid + i * 256;
        float x = X[off + c];
        if (R) x += R[off + c];
        xv[i] = x; lsum += x;
    }
    red[tid] = lsum; __syncthreads();
    for (int s = 128; s > 0; s >>= 1) { if (tid < s) red[tid] += red[tid + s]; __syncthreads(); }
    float mean = red[0] * (1.f / HD_);
    __syncthreads();
    float lvar = 0.f;
#pragma unroll
    for (int i = 0; i < 8; i++) { float d = xv[i] - mean; lvar += d * d; }
    red[tid] = lvar; __syncthreads();
    for (int s = 128; s > 0; s >>= 1) { if (tid < s) red[tid] += red[tid + s]; __syncthreads(); }
    float inv = rsqrtf(red[0] * (1.f / HD_) + 1e-5f);
#pragma unroll
    for (int i = 0; i < 8; i++) {
        int c = tid + i * 256;
        float o = (xv[i] - mean) * inv * g[c] + b[c];
        if (O) O[off + c] = o;
        O2[off + c] = __float2half(o);
    }
}

__global__ __launch_bounds__(256) void embed_kernel(
    const int* __restrict__ ids, const float* __restrict__ tok,
    const float* __restrict__ pos, float* __restrict__ h, __half* __restrict__ hh)
{
    long long idx = (long long)blockIdx.x * 256 + threadIdx.x;
    int c = (int)(idx & (HD_ - 1));
    int s = (int)(idx >> 11);
    float v = tok[(long long)ids[s] * HD_ + c] + pos[idx];
    h[idx] = v;
    hh[idx] = __float2half(v);
}

__global__ __launch_bounds__(256) void init_bias_kernel(
    const float* __restrict__ b, float* __restrict__ o)
{
    long long idx = (long long)blockIdx.x * 256 + threadIdx.x;
    o[idx] = b[idx & (HD_ - 1)];
}

// packed QKV weights + biases
__global__ __launch_bounds__(256) void pack_wqkv_kernel(
    const float* __restrict__ Wq, const float* __restrict__ Wk,
    const float* __restrict__ Wv,
    const float* __restrict__ bq, const float* __restrict__ bk,
    const float* __restrict__ bv,
    float* __restrict__ Wqkv, float* __restrict__ bqkv)
{
    const long long NW = (long long)L_ * HD_ * QKV_;
    long long idx = (long long)blockIdx.x * 256 + threadIdx.x;
    if (idx < NW) {
        int col = (int)(idx % QKV_);
        long long rk = idx / QKV_;
        int k = (int)(rk & (HD_ - 1));
        int l = (int)(rk >> 11);
        float v;
        if (col < 256) {
            int gg = col >> 6, d = col & 63;
            const float* row = Wq + (((long long)l * HD_ + k) * HD_) + gg * (GS_ * D_) + d;
            float s = 0.f;
#pragma unroll
            for (int j = 0; j < GS_; j++) s += row[j * D_];
            v = s;
        } else if (col < 512) {
            v = Wk[((long long)l * HD_ + k) * GD_ + (col - 256)];
        } else {
            v = Wv[((long long)l * HD_ + k) * GD_ + (col - 512)];
        }
        Wqkv[idx] = v;
    } else if (idx < NW + L_ * QKV_) {
        int bi  = (int)(idx - NW);
        int col = bi % QKV_;
        int l   = bi / QKV_;
        float v;
        if (col < 256) {
            int gg = col >> 6, d = col & 63;
            const float* row = bq + (long long)l * HD_ + gg * (GS_ * D_) + d;
            float s = 0.f;
#pragma unroll
            for (int j = 0; j < GS_; j++) s += row[j * D_];
            v = s;
        } else if (col < 512) v = bk[(long long)l * GD_ + (col - 256)];
        else v = bv[(long long)l * GD_ + (col - 512)];
        bqkv[bi] = v;
    }
}

__global__ __launch_bounds__(256) void reduce_wo_kernel(
    const float* __restrict__ Wo, float* __restrict__ Wo_r)
{
    long long idx = (long long)blockIdx.x * 256 + threadIdx.x;
    int n = (int)(idx & (HD_ - 1));
    int gd = (int)((idx >> 11) & (GD_ - 1));
    int l = (int)(idx >> 19);
    int gg = gd >> 6, d = gd & 63;
    float s = 0.f;
#pragma unroll
    for (int j = 0; j < GS_; j++)
        s += Wo[(((long long)l * HD_) + gg * (GS_ * D_) + j * D_ + d) * HD_ + n];
    Wo_r[idx] = s;
}

// dst(half)[c][r] = src(fp32)[r][c]; 32x32 tiles
__global__ __launch_bounds__(256) void transpose_half_kernel(
    const float* __restrict__ src, __half* __restrict__ dst, int R, int C)
{
    __shared__ float t[32][33];
    int r0 = blockIdx.y * 32, c0 = blockIdx.x * 32;
    int tx = threadIdx.x & 7, ty = threadIdx.x >> 3;
    float4 v = *(const float4*)(src + (long long)(r0 + ty) * C + c0 + tx * 4);
    t[ty][tx * 4 + 0] = v.x;
    t[ty][tx * 4 + 1] = v.y;
    t[ty][tx * 4 + 2] = v.z;
    t[ty][tx * 4 + 3] = v.w;
    __syncthreads();
    __half2 o01 = __floats2half2_rn(t[tx * 4 + 0][ty], t[tx * 4 + 1][ty]);
    __half2 o23 = __floats2half2_rn(t[tx * 4 + 2][ty], t[tx * 4 + 3][ty]);
    __half2* d = (__half2*)(dst + (long long)(c0 + ty) * R + r0 + tx * 4);
    d[0] = o01; d[1] = o23;
}

// vth[gd][t] = qkvh[t][512+gd]
__global__ __launch_bounds__(256) void transpose_v_kernel(
    const __half* __restrict__ qkv, __half* __restrict__ vt)
{
    __shared__ __half t[32][33];
    int c0 = blockIdx.x * 32;   // gd
    int r0 = blockIdx.y * 32;   // t
    int tx = threadIdx.x & 31, ty = threadIdx.x >> 5;
#pragma unroll
    for (int j = 0; j < 4; j++)
        t[ty + j * 8][tx] = qkv[(long long)(r0 + ty + j * 8) * QKV_ + 512 + c0 + tx];
    __syncthreads();
#pragma unroll
    for (int j = 0; j < 4; j++)
        vt[(long long)(c0 + ty + j * 8) * S_ + r0 + tx] = t[tx][ty + j * 8];
}

// ---------------- host ----------------
static const int SMEM_H128 = 3 * (128 + 128) * 128;   // 98304
static const int SMEM_H64  = 3 * (128 + 64) * 128;    // 73728

extern "C" void kernel_launch(void* const* d_in, const int* in_sizes, int n_in,
                              void* d_out, int out_size)
{
    const int*   ids     = (const int*)  d_in[0];
    const float* tok_emb = (const float*)d_in[1];
    const float* pos_emb = (const float*)d_in[2];
    const float* Wq  = (const float*)d_in[3];
    const float* bq  = (const float*)d_in[4];
    const float* Wk  = (const float*)d_in[5];
    const float* bk  = (const float*)d_in[6];
    const float* Wv  = (const float*)d_in[7];
    const float* bv  = (const float*)d_in[8];
    const float* Wo  = (const float*)d_in[9];
    const float* bo  = (const float*)d_in[10];
    const float* g1  = (const float*)d_in[11];
    const float* be1 = (const float*)d_in[12];
    const float* W1  = (const float*)d_in[13];
    const float* b1  = (const float*)d_in[14];
    const float* W2  = (const float*)d_in[15];
    const float* b2  = (const float*)d_in[16];
    const float* g2  = (const float*)d_in[17];
    const float* be2 = (const float*)d_in[18];
    const float* lnf_g = (const float*)d_in[19];
    const float* lnf_b = (const float*)d_in[20];
    const float* Whead = (const float*)d_in[21];
    float* out = (float*)d_out;

    cudaFuncSetAttribute(gemm_h<128>, cudaFuncAttributeMaxDynamicSharedMemorySize, SMEM_H128);
    cudaFuncSetAttribute(gemm_h<64>,  cudaFuncAttributeMaxDynamicSharedMemorySize, SMEM_H64);

    float *Wqkv, *bqkv, *Wo_r, *h, *t2, *sc;
    __half *hh, *qkvh, *vth, *sch, *ctxh, *a1h;
    __half *WqkvTh, *WoTh, *W1Th, *W2Th, *WheadTh;
    cudaGetSymbolAddress((void**)&Wqkv, g_Wqkv);
    cudaGetSymbolAddress((void**)&bqkv, g_bqkv);
    cudaGetSymbolAddress((void**)&Wo_r, g_Wo_r);
    cudaGetSymbolAddress((void**)&h,    g_h);
    cudaGetSymbolAddress((void**)&t2,   g_t2);
    cudaGetSymbolAddress((void**)&sc,   g_sc);
    cudaGetSymbolAddress((void**)&hh,   g_hh);
    cudaGetSymbolAddress((void**)&qkvh, g_qkvh);
    cudaGetSymbolAddress((void**)&vth,  g_vth);
    cudaGetSymbolAddress((void**)&sch,  g_sch);
    cudaGetSymbolAddress((void**)&ctxh, g_ctxh);
    cudaGetSymbolAddress((void**)&a1h,  g_a1h);
    cudaGetSymbolAddress((void**)&WqkvTh, g_WqkvTh);
    cudaGetSymbolAddress((void**)&WoTh,   g_WoTh);
    cudaGetSymbolAddress((void**)&W1Th,   g_W1Th);
    cudaGetSymbolAddress((void**)&W2Th,   g_W2Th);
    cudaGetSymbolAddress((void**)&WheadTh, g_WheadTh);

    // #1 embed, #2 pack QKV, #3 transpose QKV weights (l0), #4 QKV GEMM (ncu target)
    embed_kernel<<<(S_ * HD_) / 256, 256>>>(ids, tok_emb, pos_emb, h, hh);
    long long npk = (long long)L_ * HD_ * QKV_ + L_ * QKV_;
    pack_wqkv_kernel<<<(int)((npk + 255) / 256), 256>>>(Wq, Wk, Wv, bq, bk, bv, Wqkv, bqkv);
    transpose_half_kernel<<<dim3(QKV_ / 32, HD_ / 32), 256>>>(Wqkv, WqkvTh, HD_, QKV_);
    gemm_h<64><<<dim3(S_ / 128, QKV_ / 64, 1), 128, SMEM_H64>>>(
        hh, HD_, 0, WqkvTh, HD_, 0, bqkv, qkvh, QKV_, 0, HD_ / 64, 0, 1.f, 8);

    // remaining weight prep
    reduce_wo_kernel<<<(L_ * GD_ * HD_) / 256, 256>>>(Wo, Wo_r);
    transpose_half_kernel<<<dim3(QKV_ / 32, HD_ / 32), 256>>>(
        Wqkv + (long long)HD_ * QKV_, WqkvTh + (long long)QKV_ * HD_, HD_, QKV_);
    for (int l = 0; l < L_; l++) {
        transpose_half_kernel<<<dim3(HD_ / 32, GD_ / 32), 256>>>(
            Wo_r + (long long)l * GD_ * HD_, WoTh + (long long)l * HD_ * GD_, GD_, HD_);
        transpose_half_kernel<<<dim3(FF_ / 32, HD_ / 32), 256>>>(
            W1 + (long long)l * HD_ * FF_, W1Th + (long long)l * FF_ * HD_, HD_, FF_);
        transpose_half_kernel<<<dim3(HD_ / 32, FF_ / 32), 256>>>(
            W2 + (long long)l * FF_ * HD_, W2Th + (long long)l * HD_ * FF_, FF_, HD_);
    }
    transpose_half_kernel<<<dim3(V_ / 32, HD_ / 32), 256>>>(Whead, WheadTh, HD_, V_);

    for (int l = 0; l < L_; l++) {
        const __half* WqkvTh_l = WqkvTh + (long long)l * QKV_ * HD_;
        const float*  bqkv_l   = bqkv   + (long long)l * QKV_;
        const __half* WoTh_l   = WoTh   + (long long)l * HD_ * GD_;
        const __half* W1Th_l   = W1Th   + (long long)l * FF_ * HD_;
        const __half* W2Th_l   = W2Th   + (long long)l * HD_ * FF_;

        if (l > 0) {
            gemm_h<64><<<dim3(S_ / 128, QKV_ / 64, 1), 128, SMEM_H64>>>(
                hh, HD_, 0, WqkvTh_l, HD_, 0, bqkv_l, qkvh, QKV_, 0, HD_ / 64, 0, 1.f, 8);
        }

        transpose_v_kernel<<<dim3(GD_ / 32, S_ / 32), 256>>>(qkvh, vth);

        // scores[g] = 1/8 * Q_g @ K_g^T   (K=64 -> T=1)
        gemm_h<128><<<dim3(S_ / 128, S_ / 128, G_), 128, SMEM_H128>>>(
            qkvh, QKV_, 64, qkvh + 256, QKV_, 64, nullptr,
            sc, S_, (long long)S_ * S_, 1, 0, 0.125f, 0);

        softmax_kernel<<<G_ * S_, 256>>>(sc, sch, S_);

        // ctx[g] = attn_g @ V_g
        gemm_h<64><<<dim3(S_ / 128, 1, G_), 128, SMEM_H64>>>(
            sch, S_, (long long)S_ * S_, vth, S_, (long long)D_ * S_, nullptr,
            ctxh, GD_, 64, S_ / 64, 0, 1.f, 8);

        // attn_out = ctx @ Wo_r + bo ; h = LN(h + attn_out)
        gemm_h<128><<<dim3(S_ / 128, HD_ / 128, 1), 128, SMEM_H128>>>(
            ctxh, GD_, 0, WoTh_l, GD_, 0, bo + (long long)l * HD_,
            t2, HD_, 0, GD_ / 64, 0, 1.f, 0);
        ln_kernel<<<S_, 256>>>(h, t2, g1 + (long long)l * HD_, be1 + (long long)l * HD_, h, hh);

        // FFN
        gemm_h<128><<<dim3(S_ / 128, FF_ / 128, 1), 128, SMEM_H128>>>(
            hh, HD_, 0, W1Th_l, HD_, 0, b1 + (long long)l * FF_,
            a1h, FF_, 0, HD_ / 64, 0, 1.f, 1 | 8);
        init_bias_kernel<<<(S_ * HD_) / 256, 256>>>(b2 + (long long)l * HD_, t2);
        gemm_h<128><<<dim3(S_ / 128, HD_ / 128, 2), 128, SMEM_H128>>>(
            a1h, FF_, 0, W2Th_l, FF_, 0, nullptr,
            t2, HD_, 0, FF_ / 64 / 2, (long long)(FF_ / 2), 1.f, 4);
        ln_kernel<<<S_, 256>>>(h, t2, g2 + (long long)l * HD_, be2 + (long long)l * HD_, h, hh);
    }

    // final LN + lm head
    ln_kernel<<<S_, 256>>>(h, nullptr, lnf_g, lnf_b, nullptr, hh);
    gemm_h<128><<<dim3(S_ / 128, V_ / 128, 1), 128, SMEM_H128>>>(
        hh, HD_, 0, WheadTh, HD_, 0, nullptr,
        out, V_, 0, HD_ / 64, 0, 1.f, 0);
}

// round 17
// speedup vs baseline: 1.0331x; 1.0331x over previous
#include <cuda_runtime.h>
#include <cuda_fp16.h>
#include <math.h>
#include <stdint.h>

#define S_   1024
#define HD_  2048
#define L_   2
#define G_   4
#define D_   64
#define GS_  8
#define GD_  256
#define QKV_ 768
#define FF_  8192
#define V_   38400

// ---------------- scratch ----------------
__device__ float  g_bqkv[L_ * QKV_];
__device__ float  g_h  [S_ * HD_];
__device__ float  g_t2 [S_ * HD_];
__device__ float  g_sc [G_ * S_ * S_];
__device__ __half g_hh  [S_ * HD_];
__device__ __half g_qkvh[S_ * QKV_];
__device__ __half g_sch [G_ * S_ * S_];
__device__ __half g_ctxh[S_ * GD_];
__device__ __half g_a1h [S_ * FF_];
__device__ __half g_Wqkvh[L_ * HD_ * QKV_];   // [k][n] fp16
__device__ __half g_Woh  [L_ * GD_ * HD_];    // [k][n] fp16 (j-reduced)
__device__ __half g_W1h  [L_ * HD_ * FF_];
__device__ __half g_W2h  [L_ * FF_ * HD_];
__device__ __half g_Wheadh[(long long)HD_ * V_];

// ---------------- helpers ----------------
__device__ __forceinline__ void cp16(uint32_t d, const void* g) {
    asm volatile("cp.async.cg.shared.global [%0], [%1], 16;\n" :: "r"(d), "l"(g));
}
__device__ __forceinline__ void ldx4(uint32_t* r, uint32_t addr) {
    asm volatile("ldmatrix.sync.aligned.m8n8.x4.shared.b16 {%0,%1,%2,%3}, [%4];"
                 : "=r"(r[0]), "=r"(r[1]), "=r"(r[2]), "=r"(r[3]) : "r"(addr));
}
__device__ __forceinline__ void ldx4t(uint32_t* r, uint32_t addr) {
    asm volatile("ldmatrix.sync.aligned.m8n8.x4.trans.shared.b16 {%0,%1,%2,%3}, [%4];"
                 : "=r"(r[0]), "=r"(r[1]), "=r"(r[2]), "=r"(r[3]) : "r"(addr));
}
__device__ __forceinline__ void mma_f16(float c[4], const uint32_t a[4], const uint32_t b[2]) {
    asm volatile(
        "mma.sync.aligned.m16n8k16.row.col.f32.f16.f16.f32 "
        "{%0,%1,%2,%3}, {%4,%5,%6,%7}, {%8,%9}, {%0,%1,%2,%3};"
        : "+f"(c[0]), "+f"(c[1]), "+f"(c[2]), "+f"(c[3])
        : "r"(a[0]), "r"(a[1]), "r"(a[2]), "r"(a[3]), "r"(b[0]), "r"(b[1]));
}

// ---------------------------------------------------------------------------
// fp16 GEMM via ldmatrix-fed mma.sync m16n8k16, fp32 accumulate.
// BKMAJ=0: C = alpha * A[M,K] @ Bt[N,K]^T   (B rows are n, non-trans ldmatrix)
// BKMAJ=1: C = alpha * A[M,K] @ B[K,N]      (B rows are k, trans ldmatrix)
// Block 128 x BN_ x 64, 128 threads (2x2 warps, warp tile 64 x BN_/2).
// 2-stage cp.async double buffer (R14 structure).
// flags: 1=relu, 4=atomicAdd(fp32 C), 8=C is __half
// ---------------------------------------------------------------------------
template<int BN_, int BKMAJ>
__global__ __launch_bounds__(128, 2) void gemm_h(
    const __half* __restrict__ A, long long lda, long long sA,
    const __half* __restrict__ B, long long ldb, long long sB,
    const float* __restrict__ bias,
    void* __restrict__ Cv, long long ldc, long long sC,
    int kchunks, long long kbz, float alpha, int flags)
{
    constexpr int NI = BN_ / 16;
    constexpr int NCH = BN_ / 8;              // 16B chunks per B k-row (BKMAJ)
    constexpr int ABYTES = 128 * 128;
    constexpr int STAGE  = ABYTES + BN_ * 128;
    extern __shared__ char dsm[];
    const uint32_t base = (uint32_t)__cvta_generic_to_shared(dsm);

    const long long bz = blockIdx.z;
    A += bz * sA;
    B += bz * sB;
    const long long kb = bz * kbz;

    const int tid  = threadIdx.x;
    const int lane = tid & 31;
    const int warp = tid >> 5;
    const int wm   = (warp & 1) * 64;
    const int wn   = (warp >> 1) * (BN_ / 2);
    const int gid  = lane >> 2;
    const int tg   = lane & 3;
    const int row0 = blockIdx.x * 128;
    const int col0 = blockIdx.y * BN_;

    const int rowA = lane & 15;
    const int acb  = (lane >> 4) & 1;
    const uint32_t amask = (uint32_t)(rowA & 7);
    // non-trans B (BKMAJ=0)
    const int rowB = (lane & 7) + ((lane >> 4) << 3);
    const int bcb  = (lane >> 3) & 1;
    const uint32_t bmask = (uint32_t)(rowB & 7);
    // trans B (BKMAJ=1): lane -> (tile, row-within-tile)
    const int btile = lane >> 3;              // 0..3
    const int brow  = lane & 7;

    const int T = kchunks;

    auto load_chunk = [&](int i, int buf) {
        const long long k0 = kb + (long long)i * 64;
        const uint32_t sb = base + buf * STAGE;
#pragma unroll
        for (int p = 0; p < 8; p++) {                       // A: 128 rows x 8 chunks
            int v = p * 128 + tid;
            int row = v >> 3, ch = v & 7;
            cp16(sb + (uint32_t)(row * 128 + ((ch ^ (row & 7)) << 4)),
                 A + (long long)(row0 + row) * lda + k0 + ch * 8);
        }
        if (BKMAJ) {
#pragma unroll
            for (int p = 0; p < 64 * NCH / 128; p++) {      // B: 64 k-rows x NCH chunks
                int v = p * 128 + tid;
                int row = v / NCH, c = v % NCH;
                uint32_t sw = (uint32_t)(((c & 7) ^ (row & 7)) | (c & ~7));
                cp16(sb + (uint32_t)(ABYTES + row * (BN_ * 2) + (sw << 4)),
                     B + (k0 + row) * ldb + col0 + c * 8);
            }
        } else {
#pragma unroll
            for (int p = 0; p < BN_ / 16; p++) {            // B: BN n-rows x 8 chunks
                int v = p * 128 + tid;
                int row = v >> 3, ch = v & 7;
                cp16(sb + (uint32_t)(ABYTES + row * 128 + ((ch ^ (row & 7)) << 4)),
                     B + (long long)(col0 + row) * ldb + k0 + ch * 8);
            }
        }
        asm volatile("cp.async.commit_group;\n" ::);
    };

    float acc[4][NI][4];
#pragma unroll
    for (int mi = 0; mi < 4; mi++)
#pragma unroll
        for (int ni = 0; ni < NI; ni++)
#pragma unroll
            for (int c = 0; c < 4; c++) acc[mi][ni][c] = 0.f;

    load_chunk(0, 0);
    if (T > 1) {
        load_chunk(1, 1);
        asm volatile("cp.async.wait_group 1;\n" ::);
    } else {
        asm volatile("cp.async.wait_group 0;\n" ::);
    }
    __syncthreads();

    for (int i = 0; i < T; i++) {
        const int buf = i & 1;
        const uint32_t Ab = base + buf * STAGE;
        const uint32_t Bb = Ab + ABYTES;

#pragma unroll
        for (int ks = 0; ks < 4; ks++) {        // 4 k16 slices per 64-k chunk
            const uint32_t ca = (uint32_t)(ks * 2 + acb);
            uint32_t afr[4][4];
#pragma unroll
            for (int mi = 0; mi < 4; mi++) {
                uint32_t r = (uint32_t)(wm + mi * 16 + rowA);
                ldx4(afr[mi], Ab + r * 128 + ((ca ^ amask) << 4));
            }
            uint32_t bfr[NI][2];
#pragma unroll
            for (int p = 0; p < NI / 2; p++) {
                uint32_t q[4];
                if (BKMAJ) {
                    int krow = ks * 16 + (btile & 1) * 8 + brow;
                    int ncol = wn + p * 16 + (btile >> 1) * 8;
                    int c = ncol >> 3;
                    uint32_t sw = (uint32_t)(((c & 7) ^ (krow & 7)) | (c & ~7));
                    ldx4t(q, Bb + krow * (BN_ * 2) + (sw << 4));
                } else {
                    const uint32_t cb = (uint32_t)(ks * 2 + bcb);
                    uint32_t r = (uint32_t)(wn + p * 16 + rowB);
                    ldx4(q, Bb + r * 128 + ((cb ^ bmask) << 4));
                }
                bfr[2 * p][0] = q[0]; bfr[2 * p][1] = q[1];
                bfr[2 * p + 1][0] = q[2]; bfr[2 * p + 1][1] = q[3];
            }
#pragma unroll
            for (int mi = 0; mi < 4; mi++)
#pragma unroll
                for (int ni = 0; ni < NI; ni++)
                    mma_f16(acc[mi][ni], afr[mi], bfr[ni]);
        }

        if (i + 1 < T) {
            __syncthreads();
            if (i + 2 < T) {
                load_chunk(i + 2, buf);
                asm volatile("cp.async.wait_group 1;\n" ::);
            } else {
                asm volatile("cp.async.wait_group 0;\n" ::);
            }
            __syncthreads();
        }
    }

    float*  Cf = (float*)Cv + bz * sC;
    __half* Ch = (__half*)Cv + bz * sC;
#pragma unroll
    for (int mi = 0; mi < 4; mi++) {
        int m0 = row0 + wm + mi * 16 + gid;
#pragma unroll
        for (int ni = 0; ni < NI; ni++) {
            int n = col0 + wn + ni * 8 + tg * 2;
            float v0 = alpha * acc[mi][ni][0];
            float v1 = alpha * acc[mi][ni][1];
            float v2 = alpha * acc[mi][ni][2];
            float v3 = alpha * acc[mi][ni][3];
            if (flags & 4) {
                atomicAdd(Cf + (long long)m0 * ldc + n, v0);
                atomicAdd(Cf + (long long)m0 * ldc + n + 1, v1);
                atomicAdd(Cf + (long long)(m0 + 8) * ldc + n, v2);
                atomicAdd(Cf + (long long)(m0 + 8) * ldc + n + 1, v3);
            } else {
                if (bias) {
                    float b0 = bias[n], b1 = bias[n + 1];
                    v0 += b0; v1 += b1; v2 += b0; v3 += b1;
                }
                if (flags & 1) {
                    v0 = fmaxf(v0, 0.f); v1 = fmaxf(v1, 0.f);
                    v2 = fmaxf(v2, 0.f); v3 = fmaxf(v3, 0.f);
                }
                if (flags & 8) {
                    *(__half2*)(Ch + (long long)m0 * ldc + n)       = __floats2half2_rn(v0, v1);
                    *(__half2*)(Ch + (long long)(m0 + 8) * ldc + n) = __floats2half2_rn(v2, v3);
                } else {
                    *(float2*)(Cf + (long long)m0 * ldc + n)       = make_float2(v0, v1);
                    *(float2*)(Cf + (long long)(m0 + 8) * ldc + n) = make_float2(v2, v3);
                }
            }
        }
    }
}

// ---------------- elementwise kernels ----------------
__global__ __launch_bounds__(256) void softmax_kernel(
    const float* __restrict__ Srows, __half* __restrict__ Orows, int T)
{
    const float* row = Srows + (long long)blockIdx.x * T;
    __half* orow = Orows + (long long)blockIdx.x * T;
    __shared__ float red[256];
    int tid = threadIdx.x;
    float m = -INFINITY;
    for (int i = tid; i < T; i += 256) m = fmaxf(m, row[i]);
    red[tid] = m; __syncthreads();
    for (int s = 128; s > 0; s >>= 1) { if (tid < s) red[tid] = fmaxf(red[tid], red[tid + s]); __syncthreads(); }
    m = red[0]; __syncthreads();
    float sum = 0.f;
    float ev[4];
#pragma unroll
    for (int j = 0; j < 4; j++) {
        ev[j] = expf(row[tid + j * 256] - m);
        sum += ev[j];
    }
    red[tid] = sum; __syncthreads();
    for (int s = 128; s > 0; s >>= 1) { if (tid < s) red[tid] += red[tid + s]; __syncthreads(); }
    float inv = 1.f / red[0];
#pragma unroll
    for (int j = 0; j < 4; j++)
        orow[tid + j * 256] = __float2half(ev[j] * inv);
}

__global__ __launch_bounds__(256) void ln_kernel(
    const float* __restrict__ X, const float* __restrict__ R,
    const float* __restrict__ g, const float* __restrict__ b,
    float* __restrict__ O, __half* __restrict__ O2)
{
    long long off = (long long)blockIdx.x * HD_;
    __shared__ float red[256];
    int tid = threadIdx.x;
    float xv[8];
    float lsum = 0.f;
#pragma unroll
    for (int i = 0; i < 8; i++) {
        int c = tid + i * 256;
        float x = X[off + c];
        if (R) x += R[off + c];
        xv[i] = x; lsum += x;
    }
    red[tid] = lsum; __syncthreads();
    for (int s = 128; s > 0; s >>= 1) { if (tid < s) red[tid] += red[tid + s]; __syncthreads(); }
    float mean = red[0] * (1.f / HD_);
    __syncthreads();
    float lvar = 0.f;
#pragma unroll
    for (int i = 0; i < 8; i++) { float d = xv[i] - mean; lvar += d * d; }
    red[tid] = lvar; __syncthreads();
    for (int s = 128; s > 0; s >>= 1) { if (tid < s) red[tid] += red[tid + s]; __syncthreads(); }
    float inv = rsqrtf(red[0] * (1.f / HD_) + 1e-5f);
#pragma unroll
    for (int i = 0; i < 8; i++) {
        int c = tid + i * 256;
        float o = (xv[i] - mean) * inv * g[c] + b[c];
        if (O) O[off + c] = o;
        O2[off + c] = __float2half(o);
    }
}

__global__ __launch_bounds__(256) void embed_kernel(
    const int* __restrict__ ids, const float* __restrict__ tok,
    const float* __restrict__ pos, float* __restrict__ h, __half* __restrict__ hh)
{
    long long idx = (long long)blockIdx.x * 256 + threadIdx.x;
    int c = (int)(idx & (HD_ - 1));
    int s = (int)(idx >> 11);
    float v = tok[(long long)ids[s] * HD_ + c] + pos[idx];
    h[idx] = v;
    hh[idx] = __float2half(v);
}

__global__ __launch_bounds__(256) void init_bias_kernel(
    const float* __restrict__ b, float* __restrict__ o)
{
    long long idx = (long long)blockIdx.x * 256 + threadIdx.x;
    o[idx] = b[idx & (HD_ - 1)];
}

// straight fp32 -> fp16 convert (coalesced, float4 in, 8B out)
__global__ __launch_bounds__(256) void cvt_kernel(
    const float* __restrict__ src, __half* __restrict__ dst, long long n4)
{
    long long i = (long long)blockIdx.x * 256 + threadIdx.x;
    if (i >= n4) return;
    float4 v = *(const float4*)(src + i * 4);
    __half2* d = (__half2*)(dst + i * 4);
    d[0] = __floats2half2_rn(v.x, v.y);
    d[1] = __floats2half2_rn(v.z, v.w);
}

// packed QKV weights (fp16, [k][n]) + biases (fp32)
__global__ __launch_bounds__(256) void pack_wqkv_kernel(
    const float* __restrict__ Wq, const float* __restrict__ Wk,
    const float* __restrict__ Wv,
    const float* __restrict__ bq, const float* __restrict__ bk,
    const float* __restrict__ bv,
    __half* __restrict__ Wqkv, float* __restrict__ bqkv)
{
    const long long NW = (long long)L_ * HD_ * QKV_;
    long long idx = (long long)blockIdx.x * 256 + threadIdx.x;
    if (idx < NW) {
        int col = (int)(idx % QKV_);
        long long rk = idx / QKV_;
        int k = (int)(rk & (HD_ - 1));
        int l = (int)(rk >> 11);
        float v;
        if (col < 256) {
            int gg = col >> 6, d = col & 63;
            const float* row = Wq + (((long long)l * HD_ + k) * HD_) + gg * (GS_ * D_) + d;
            float s = 0.f;
#pragma unroll
            for (int j = 0; j < GS_; j++) s += row[j * D_];
            v = s;
        } else if (col < 512) {
            v = Wk[((long long)l * HD_ + k) * GD_ + (col - 256)];
        } else {
            v = Wv[((long long)l * HD_ + k) * GD_ + (col - 512)];
        }
        Wqkv[idx] = __float2half(v);
    } else if (idx < NW + L_ * QKV_) {
        int bi  = (int)(idx - NW);
        int col = bi % QKV_;
        int l   = bi / QKV_;
        float v;
        if (col < 256) {
            int gg = col >> 6, d = col & 63;
            const float* row = bq + (long long)l * HD_ + gg * (GS_ * D_) + d;
            float s = 0.f;
#pragma unroll
            for (int j = 0; j < GS_; j++) s += row[j * D_];
            v = s;
        } else if (col < 512) v = bk[(long long)l * GD_ + (col - 256)];
        else v = bv[(long long)l * GD_ + (col - 512)];
        bqkv[bi] = v;
    }
}

// Wo_r (j-reduced) -> fp16 [gd][n]
__global__ __launch_bounds__(256) void reduce_wo_kernel(
    const float* __restrict__ Wo, __half* __restrict__ Woh)
{
    long long idx = (long long)blockIdx.x * 256 + threadIdx.x;
    int n = (int)(idx & (HD_ - 1));
    int gd = (int)((idx >> 11) & (GD_ - 1));
    int l = (int)(idx >> 19);
    int gg = gd >> 6, d = gd & 63;
    float s = 0.f;
#pragma unroll
    for (int j = 0; j < GS_; j++)
        s += Wo[(((long long)l * HD_) + gg * (GS_ * D_) + j * D_ + d) * HD_ + n];
    Woh[idx] = __float2half(s);
}

// ---------------- host ----------------
static const int SMEM_H128 = 2 * (128 + 128) * 128;   // 65536
static const int SMEM_H64  = 2 * (128 + 64) * 128;    // 49152

extern "C" void kernel_launch(void* const* d_in, const int* in_sizes, int n_in,
                              void* d_out, int out_size)
{
    const int*   ids     = (const int*)  d_in[0];
    const float* tok_emb = (const float*)d_in[1];
    const float* pos_emb = (const float*)d_in[2];
    const float* Wq  = (const float*)d_in[3];
    const float* bq  = (const float*)d_in[4];
    const float* Wk  = (const float*)d_in[5];
    const float* bk  = (const float*)d_in[6];
    const float* Wv  = (const float*)d_in[7];
    const float* bv  = (const float*)d_in[8];
    const float* Wo  = (const float*)d_in[9];
    const float* bo  = (const float*)d_in[10];
    const float* g1  = (const float*)d_in[11];
    const float* be1 = (const float*)d_in[12];
    const float* W1  = (const float*)d_in[13];
    const float* b1  = (const float*)d_in[14];
    const float* W2  = (const float*)d_in[15];
    const float* b2  = (const float*)d_in[16];
    const float* g2  = (const float*)d_in[17];
    const float* be2 = (const float*)d_in[18];
    const float* lnf_g = (const float*)d_in[19];
    const float* lnf_b = (const float*)d_in[20];
    const float* Whead = (const float*)d_in[21];
    float* out = (float*)d_out;

    cudaFuncSetAttribute(gemm_h<128, 0>, cudaFuncAttributeMaxDynamicSharedMemorySize, SMEM_H128);
    cudaFuncSetAttribute(gemm_h<128, 1>, cudaFuncAttributeMaxDynamicSharedMemorySize, SMEM_H128);
    cudaFuncSetAttribute(gemm_h<64, 1>,  cudaFuncAttributeMaxDynamicSharedMemorySize, SMEM_H64);

    float *bqkv, *h, *t2, *sc;
    __half *hh, *qkvh, *sch, *ctxh, *a1h;
    __half *Wqkvh, *Woh, *W1h, *W2h, *Wheadh;
    cudaGetSymbolAddress((void**)&bqkv, g_bqkv);
    cudaGetSymbolAddress((void**)&h,    g_h);
    cudaGetSymbolAddress((void**)&t2,   g_t2);
    cudaGetSymbolAddress((void**)&sc,   g_sc);
    cudaGetSymbolAddress((void**)&hh,   g_hh);
    cudaGetSymbolAddress((void**)&qkvh, g_qkvh);
    cudaGetSymbolAddress((void**)&sch,  g_sch);
    cudaGetSymbolAddress((void**)&ctxh, g_ctxh);
    cudaGetSymbolAddress((void**)&a1h,  g_a1h);
    cudaGetSymbolAddress((void**)&Wqkvh, g_Wqkvh);
    cudaGetSymbolAddress((void**)&Woh,   g_Woh);
    cudaGetSymbolAddress((void**)&W1h,   g_W1h);
    cudaGetSymbolAddress((void**)&W2h,   g_W2h);
    cudaGetSymbolAddress((void**)&Wheadh, g_Wheadh);

    // #1 embed, #2 pack QKV (fp16 direct), #3 reduce Wo (fp16 direct),
    // #4 layer-0 QKV GEMM  (ncu capture target)
    embed_kernel<<<(S_ * HD_) / 256, 256>>>(ids, tok_emb, pos_emb, h, hh);
    long long npk = (long long)L_ * HD_ * QKV_ + L_ * QKV_;
    pack_wqkv_kernel<<<(int)((npk + 255) / 256), 256>>>(Wq, Wk, Wv, bq, bk, bv, Wqkvh, bqkv);
    reduce_wo_kernel<<<(L_ * GD_ * HD_) / 256, 256>>>(Wo, Woh);
    gemm_h<64, 1><<<dim3(S_ / 128, QKV_ / 64, 1), 128, SMEM_H64>>>(
        hh, HD_, 0, Wqkvh, QKV_, 0, bqkv, qkvh, QKV_, 0, HD_ / 64, 0, 1.f, 8);

    // straight fp32->fp16 converts (no transposes needed: weights are [k][n])
    cvt_kernel<<<(int)((long long)L_ * HD_ * FF_ / 1024), 256>>>(W1, W1h, (long long)L_ * HD_ * FF_ / 4);
    cvt_kernel<<<(int)((long long)L_ * FF_ * HD_ / 1024), 256>>>(W2, W2h, (long long)L_ * FF_ * HD_ / 4);
    cvt_kernel<<<(int)(((long long)HD_ * V_ + 1023) / 1024), 256>>>(Whead, Wheadh, (long long)HD_ * V_ / 4);

    for (int l = 0; l < L_; l++) {
        const __half* Wqkvh_l = Wqkvh + (long long)l * HD_ * QKV_;
        const float*  bqkv_l  = bqkv  + (long long)l * QKV_;
        const __half* Woh_l   = Woh   + (long long)l * GD_ * HD_;
        const __half* W1h_l   = W1h   + (long long)l * HD_ * FF_;
        const __half* W2h_l   = W2h   + (long long)l * FF_ * HD_;

        if (l > 0) {
            gemm_h<64, 1><<<dim3(S_ / 128, QKV_ / 64, 1), 128, SMEM_H64>>>(
                hh, HD_, 0, Wqkvh_l, QKV_, 0, bqkv_l, qkvh, QKV_, 0, HD_ / 64, 0, 1.f, 8);
        }

        // scores[g] = 1/8 * Q_g @ K_g^T   (K rows are [t][d] -> n-major path)
        gemm_h<128, 0><<<dim3(S_ / 128, S_ / 128, G_), 128, SMEM_H128>>>(
            qkvh, QKV_, 64, qkvh + 256, QKV_, 64, nullptr,
            sc, S_, (long long)S_ * S_, 1, 0, 0.125f, 0);

        softmax_kernel<<<G_ * S_, 256>>>(sc, sch, S_);

        // ctx[g] = attn_g @ V_g   (V is naturally [t][d] = [k][n])
        gemm_h<64, 1><<<dim3(S_ / 128, 1, G_), 128, SMEM_H64>>>(
            sch, S_, (long long)S_ * S_, qkvh + 512, QKV_, 64, nullptr,
            ctxh, GD_, 64, S_ / 64, 0, 1.f, 8);

        // attn_out = ctx @ Wo_r + bo ; h = LN(h + attn_out)
        gemm_h<128, 1><<<dim3(S_ / 128, HD_ / 128, 1), 128, SMEM_H128>>>(
            ctxh, GD_, 0, Woh_l, HD_, 0, bo + (long long)l * HD_,
            t2, HD_, 0, GD_ / 64, 0, 1.f, 0);
        ln_kernel<<<S_, 256>>>(h, t2, g1 + (long long)l * HD_, be1 + (long long)l * HD_, h, hh);

        // FFN
        gemm_h<128, 1><<<dim3(S_ / 128, FF_ / 128, 1), 128, SMEM_H128>>>(
            hh, HD_, 0, W1h_l, FF_, 0, b1 + (long long)l * FF_,
            a1h, FF_, 0, HD_ / 64, 0, 1.f, 1 | 8);
        init_bias_kernel<<<(S_ * HD_) / 256, 256>>>(b2 + (long long)l * HD_, t2);
        gemm_h<128, 1><<<dim3(S_ / 128, HD_ / 128, 2), 128, SMEM_H128>>>(
            a1h, FF_, 0, W2h_l, HD_, 0, nullptr,
            t2, HD_, 0, FF_ / 64 / 2, (long long)(FF_ / 2), 1.f, 4);
        ln_kernel<<<S_, 256>>>(h, t2, g2 + (long long)l * HD_, be2 + (long long)l * HD_, h, hh);
    }

    // final LN + lm head
    ln_kernel<<<S_, 256>>>(h, nullptr, lnf_g, lnf_b, nullptr, hh);
    gemm_h<128, 1><<<dim3(S_ / 128, V_ / 128, 1), 128, SMEM_H128>>>(
        hh, HD_, 0, Wheadh, V_, 0, nullptr,
        out, V_, 0, HD_ / 64, 0, 1.f, 0);
}